// round 15
// baseline (speedup 1.0000x reference)
#include <cuda_runtime.h>

#define WD 512
#define BAND 16
#define NBATCH 16
#define ROWF 520            // 4 pad + 512 + 4 pad
#define NCC_BLOCKS 1024
#define GRAD_BLOCKS 128
#define TOTAL_BLOCKS (NCC_BLOCKS + GRAD_BLOCKS)
#define SMEM_BYTES (2 * 5 * ROWF * 4)   // 20800 B, double-buffered single row

// [0],[1]: cc sums per channel; [2]: sum dx^2; [3]: sum dy^2
__device__ double g_acc[4];
__device__ unsigned int g_count;

__global__ __launch_bounds__(128, 8) void fused_kernel(const float* __restrict__ I,
                                                       const float* __restrict__ J,
                                                       const float* __restrict__ dvf,
                                                       int n_dvf,
                                                       float* __restrict__ out) {
    extern __shared__ __align__(16) float dyn[];   // [2][5][ROWF]
    __shared__ float red[4];
    __shared__ float red2[4];
    __shared__ bool is_last;

    const int t = threadIdx.x;
    const int blk = blockIdx.x;

    if (blk < NCC_BLOCKS) {
        // ───────────────────────── NCC block ─────────────────────────
        const int img = blk >> 5;       // 32 bands per image, 32 images
        const int band = blk & 31;
        const int r0 = band * BAND;
        const size_t base = (size_t)img * (WD * WD);
        const float* __restrict__ Ip = I + base;
        const float* __restrict__ Jp = J + base;

        // zero horizontal padding (cols 0..3, 516..519) in BOTH buffers
        if (t < 4) {
#pragma unroll
            for (int bu = 0; bu < 2; bu++)
#pragma unroll
                for (int q = 0; q < 5; q++) {
                    float* row = dyn + (size_t)(bu * 5 + q) * ROWF;
                    row[t] = 0.0f;
                    row[516 + t] = 0.0f;
                }
        }

        // each thread owns 4 columns [4t, 4t+4) — float4 loads/stores
        const int c0 = 4 * t;
        float4 cs0 = make_float4(0.f, 0.f, 0.f, 0.f);
        float4 cs1 = cs0, cs2 = cs0, cs3 = cs0, cs4 = cs0;

        // vertical prime: rows [r0-4, r0+3]
#pragma unroll
        for (int k = 0; k < 8; k++) {
            int r = r0 - 4 + k;
            if (r >= 0) {
                float4 a = *(const float4*)(Ip + r * WD + c0);
                float4 b = *(const float4*)(Jp + r * WD + c0);
                cs0.x += a.x; cs0.y += a.y; cs0.z += a.z; cs0.w += a.w;
                cs1.x += b.x; cs1.y += b.y; cs1.z += b.z; cs1.w += b.w;
                cs2.x += a.x * a.x; cs2.y += a.y * a.y; cs2.z += a.z * a.z; cs2.w += a.w * a.w;
                cs3.x += b.x * b.x; cs3.y += b.y * b.y; cs3.z += b.z * b.z; cs3.w += b.w * b.w;
                cs4.x += a.x * b.x; cs4.y += a.y * b.y; cs4.z += a.z * b.z; cs4.w += a.w * b.w;
            }
        }

        // phase A: slide vertical sums one row, stage column sums into `buf`
        auto phaseA = [&](int buf, int r) {
            float4 z = make_float4(0.f, 0.f, 0.f, 0.f);
            float4 a = z, b = z;
            if (r + 4 < WD) {
                a = *(const float4*)(Ip + (r + 4) * WD + c0);
                b = *(const float4*)(Jp + (r + 4) * WD + c0);
            }
            cs0.x += a.x; cs0.y += a.y; cs0.z += a.z; cs0.w += a.w;
            cs1.x += b.x; cs1.y += b.y; cs1.z += b.z; cs1.w += b.w;
            cs2.x += a.x * a.x; cs2.y += a.y * a.y; cs2.z += a.z * a.z; cs2.w += a.w * a.w;
            cs3.x += b.x * b.x; cs3.y += b.y * b.y; cs3.z += b.z * b.z; cs3.w += b.w * b.w;
            cs4.x += a.x * b.x; cs4.y += a.y * b.y; cs4.z += a.z * b.z; cs4.w += a.w * b.w;
            float* rowp = dyn + (size_t)(buf * 5) * ROWF + 4 + c0;
            *(float4*)(rowp + 0 * ROWF) = cs0;
            *(float4*)(rowp + 1 * ROWF) = cs1;
            *(float4*)(rowp + 2 * ROWF) = cs2;
            *(float4*)(rowp + 3 * ROWF) = cs3;
            *(float4*)(rowp + 4 * ROWF) = cs4;
            float4 c = z, d = z;
            if (r - 4 >= 0) {
                c = *(const float4*)(Ip + (r - 4) * WD + c0);
                d = *(const float4*)(Jp + (r - 4) * WD + c0);
            }
            cs0.x -= c.x; cs0.y -= c.y; cs0.z -= c.z; cs0.w -= c.w;
            cs1.x -= d.x; cs1.y -= d.y; cs1.z -= d.z; cs1.w -= d.w;
            cs2.x -= c.x * c.x; cs2.y -= c.y * c.y; cs2.z -= c.z * c.z; cs2.w -= c.w * c.w;
            cs3.x -= d.x * d.x; cs3.y -= d.y * d.y; cs3.z -= d.z * d.z; cs3.w -= d.w * d.w;
            cs4.x -= c.x * d.x; cs4.y -= c.y * d.y; cs4.z -= c.z * d.z; cs4.w -= c.w * d.w;
        };

        float acc = 0.f;
        const float inv81 = 1.0f / 81.0f;

        // phase B: horizontal 9-sums + cc; pixels [4t, 4t+4) of the staged row.
        // window cols 4t-4..4t+7 -> padded float4 blocks t, t+1, t+2.
        auto phaseB = [&](int buf) {
            float S[5][4];
#pragma unroll
            for (int q = 0; q < 5; q++) {
                const float4* row4 = (const float4*)(dyn + (size_t)(buf * 5 + q) * ROWF);
                float4 A = row4[t], B = row4[t + 1], C = row4[t + 2];
                float s = A.x + A.y + A.z + A.w + B.x + B.y + B.z + B.w + C.x;
                S[q][0] = s;
                s += C.y - A.x; S[q][1] = s;
                s += C.z - A.y; S[q][2] = s;
                s += C.w - A.z; S[q][3] = s;
            }
            float num[4], den[4];
#pragma unroll
            for (int i = 0; i < 4; i++) {
                float sI = S[0][i], sJ = S[1][i];
                float sII = S[2][i], sJJ = S[3][i], sIJ = S[4][i];
                float cross = sIJ - sI * sJ * inv81;
                float Iv = sII - sI * sI * inv81;
                float Jv = sJJ - sJ * sJ * inv81;
                num[i] = cross * cross;
                den[i] = Iv * Jv + 1e-5f;
            }
            float d01 = den[0] * den[1];
            float d23 = den[2] * den[3];
            float n01 = num[0] * den[1] + num[1] * den[0];
            float n23 = num[2] * den[3] + num[3] * den[2];
            acc += __fdividef(n01 * d23 + n23 * d01, d01 * d23);
        };

        __syncthreads();              // padding visible
        phaseA(0, r0);
        __syncthreads();              // buf0 ready

        for (int b = 0; b < NBATCH; b++) {
            if (b + 1 < NBATCH) phaseA((b + 1) & 1, r0 + b + 1);   // overlaps B(b)
            phaseB(b & 1);
            __syncthreads();          // publishes A(b+1), protects buf reuse
        }

        // block reduction (4 warps)
#pragma unroll
        for (int d = 16; d > 0; d >>= 1) acc += __shfl_down_sync(0xffffffffu, acc, d);
        if ((t & 31) == 0) red[t >> 5] = acc;
        __syncthreads();
        if (t < 32) {
            float v = (t < 4) ? red[t] : 0.f;
            v += __shfl_down_sync(0xffffffffu, v, 2);
            v += __shfl_down_sync(0xffffffffu, v, 1);
            if (t == 0) atomicAdd(&g_acc[img & 1], (double)v);
        }
    } else {
        // ───────────────────────── grad block ─────────────────────────
        float adx = 0.f, ady = 0.f;
        const int gb = blk - NCC_BLOCKS;
        for (int idx = gb * 128 + t; idx < n_dvf; idx += GRAD_BLOCKS * 128) {
            const int hw = idx & 65535;           // position within one 256x256 map
            const float c = dvf[idx];
            if ((hw & 255) != 255) { float d = dvf[idx + 1] - c; adx += d * d; }
            if (hw < 65280)        { float d = dvf[idx + 256] - c; ady += d * d; }
        }
#pragma unroll
        for (int d = 16; d > 0; d >>= 1) {
            adx += __shfl_down_sync(0xffffffffu, adx, d);
            ady += __shfl_down_sync(0xffffffffu, ady, d);
        }
        if ((t & 31) == 0) { red[t >> 5] = adx; red2[t >> 5] = ady; }
        __syncthreads();
        if (t < 32) {
            float x = (t < 4) ? red[t] : 0.f;
            float y = (t < 4) ? red2[t] : 0.f;
            x += __shfl_down_sync(0xffffffffu, x, 2);
            y += __shfl_down_sync(0xffffffffu, y, 2);
            x += __shfl_down_sync(0xffffffffu, x, 1);
            y += __shfl_down_sync(0xffffffffu, y, 1);
            if (t == 0) {
                atomicAdd(&g_acc[2], (double)x);
                atomicAdd(&g_acc[3], (double)y);
            }
        }
    }

    // ───────────────── last-block finalize (graph-replay safe) ─────────────────
    __threadfence();
    if (t == 0) {
        unsigned int prev = atomicAdd(&g_count, 1u);
        is_last = (prev == (unsigned int)(TOTAL_BLOCKS - 1));
    }
    __syncthreads();
    if (is_last && t == 0) {
        // ncc = -(m0 + m1)/(C-1), C=2; m_c = sum_c / (B*H*W)
        double ncc = -(g_acc[0] + g_acc[1]) / (16.0 * 512.0 * 512.0);
        // grad = 0.01 * ((mean(dx^2)+mean(dy^2))/2 * 2.0)
        double Nd = 16.0 * 2.0 * 256.0 * 255.0;
        double grad = 0.01 * (g_acc[2] / Nd + g_acc[3] / Nd);
        out[0] = (float)(ncc + grad);
        out[1] = (float)ncc;
        out[2] = (float)grad;
        g_acc[0] = 0.0; g_acc[1] = 0.0; g_acc[2] = 0.0; g_acc[3] = 0.0;
        g_count = 0u;
    }
}

extern "C" void kernel_launch(void* const* d_in, const int* in_sizes, int n_in,
                              void* d_out, int out_size) {
    const float* y_true = (const float*)d_in[0];
    const float* y_pred = (const float*)d_in[1];
    const float* dvf    = (const float*)d_in[2];
    float* out = (float*)d_out;
    const int n_dvf = in_sizes[2];

    cudaFuncSetAttribute(fused_kernel, cudaFuncAttributeMaxDynamicSharedMemorySize,
                         SMEM_BYTES);
    fused_kernel<<<TOTAL_BLOCKS, 128, SMEM_BYTES>>>(y_true, y_pred, dvf, n_dvf, out);
}

// round 16
// speedup vs baseline: 1.0555x; 1.0555x over previous
#include <cuda_runtime.h>

#define WD 512
#define BAND 16
#define RB 2
#define NBATCH 8
#define ROWF 520            // 4 pad + 512 + 4 pad
#define NCC_BLOCKS 1024
#define GRAD_BLOCKS 128
#define TOTAL_BLOCKS (NCC_BLOCKS + GRAD_BLOCKS)
#define SMEM_BYTES (2 * RB * 5 * ROWF * 4)   // 41600 B, double-buffered

// [0],[1]: cc sums per channel; [2]: sum dx^2; [3]: sum dy^2
__device__ double g_acc[4];
__device__ unsigned int g_count;

// Full NCC pipeline for one 16-row band. G = boundary guards needed
// (only bands 0 and 31). Uniform per block -> barriers are safe.
template <bool G>
__device__ __forceinline__ float ncc_pipeline(const float* __restrict__ Ip,
                                              const float* __restrict__ Jp,
                                              float* __restrict__ dyn,
                                              const int r0, const int t) {
    const int c0 = 2 * t;            // thread owns columns 2t, 2t+1
    float ca0 = 0.f, ca1 = 0.f, ca2 = 0.f, ca3 = 0.f, ca4 = 0.f;   // col 2t
    float cb0 = 0.f, cb1 = 0.f, cb2 = 0.f, cb3 = 0.f, cb4 = 0.f;   // col 2t+1

    // vertical prime: rows [r0-4, r0+3]
#pragma unroll
    for (int k = 0; k < 8; k++) {
        const int r = r0 - 4 + k;
        if (!G || r >= 0) {
            float2 a = *(const float2*)(Ip + r * WD + c0);
            float2 b = *(const float2*)(Jp + r * WD + c0);
            ca0 += a.x; ca1 += b.x; ca2 += a.x * a.x; ca3 += b.x * b.x; ca4 += a.x * b.x;
            cb0 += a.y; cb1 += b.y; cb2 += a.y * a.y; cb3 += b.y * b.y; cb4 += a.y * b.y;
        }
    }

    // phase A: slide vertical sums over RB rows, stage column sums
    auto phaseA = [&](int buf, int rbase) {
#pragma unroll
        for (int rr = 0; rr < RB; rr++) {
            const int r = rbase + rr;
            float2 a = make_float2(0.f, 0.f), b = make_float2(0.f, 0.f);
            if (!G || r + 4 < WD) {
                a = *(const float2*)(Ip + (r + 4) * WD + c0);
                b = *(const float2*)(Jp + (r + 4) * WD + c0);
            }
            ca0 += a.x; ca1 += b.x; ca2 += a.x * a.x; ca3 += b.x * b.x; ca4 += a.x * b.x;
            cb0 += a.y; cb1 += b.y; cb2 += a.y * a.y; cb3 += b.y * b.y; cb4 += a.y * b.y;
            float* rowp = dyn + (size_t)((buf * RB + rr) * 5) * ROWF + 4 + c0;
            *(float2*)(rowp + 0 * ROWF) = make_float2(ca0, cb0);
            *(float2*)(rowp + 1 * ROWF) = make_float2(ca1, cb1);
            *(float2*)(rowp + 2 * ROWF) = make_float2(ca2, cb2);
            *(float2*)(rowp + 3 * ROWF) = make_float2(ca3, cb3);
            *(float2*)(rowp + 4 * ROWF) = make_float2(ca4, cb4);
            float2 c = make_float2(0.f, 0.f), d = make_float2(0.f, 0.f);
            if (!G || r - 4 >= 0) {
                c = *(const float2*)(Ip + (r - 4) * WD + c0);
                d = *(const float2*)(Jp + (r - 4) * WD + c0);
            }
            ca0 -= c.x; ca1 -= d.x; ca2 -= c.x * c.x; ca3 -= d.x * d.x; ca4 -= c.x * d.x;
            cb0 -= c.y; cb1 -= d.y; cb2 -= c.y * c.y; cb3 -= d.y * d.y; cb4 -= c.y * d.y;
        }
    };

    float acc = 0.f;
    const int rsB = t >> 7;          // which of the 2 staged rows
    const int seg = t & 127;         // 4-column run: cols [seg*4, seg*4+4)
    const float inv81 = 1.0f / 81.0f;

    // phase B: horizontal 9-sums + cc; 4 divides batched into one.
    auto phaseB = [&](int buf) {
        float S[5][4];
#pragma unroll
        for (int q = 0; q < 5; q++) {
            const float4* row4 =
                (const float4*)(dyn + (size_t)((buf * RB + rsB) * 5 + q) * ROWF);
            float4 A = row4[seg], B = row4[seg + 1], C = row4[seg + 2];
            float s = A.x + A.y + A.z + A.w + B.x + B.y + B.z + B.w + C.x;
            S[q][0] = s;
            s += C.y - A.x; S[q][1] = s;
            s += C.z - A.y; S[q][2] = s;
            s += C.w - A.z; S[q][3] = s;
        }
        float num[4], den[4];
#pragma unroll
        for (int i = 0; i < 4; i++) {
            float sI = S[0][i], sJ = S[1][i];
            float sII = S[2][i], sJJ = S[3][i], sIJ = S[4][i];
            float cross = sIJ - sI * sJ * inv81;
            float Iv = sII - sI * sI * inv81;
            float Jv = sJJ - sJ * sJ * inv81;
            num[i] = cross * cross;
            den[i] = Iv * Jv + 1e-5f;
        }
        float d01 = den[0] * den[1];
        float d23 = den[2] * den[3];
        float n01 = num[0] * den[1] + num[1] * den[0];
        float n23 = num[2] * den[3] + num[3] * den[2];
        acc += __fdividef(n01 * d23 + n23 * d01, d01 * d23);
    };

    phaseA(0, r0);
    __syncthreads();                 // publishes padding + buf0 together

#pragma unroll 2
    for (int b = 0; b < NBATCH; b++) {
        if (b + 1 < NBATCH) phaseA((b + 1) & 1, r0 + (b + 1) * RB);  // overlaps B(b)
        phaseB(b & 1);
        __syncthreads();             // publishes A(b+1), protects buf reuse
    }
    return acc;
}

__global__ __launch_bounds__(256, 4) void fused_kernel(const float* __restrict__ I,
                                                       const float* __restrict__ J,
                                                       const float* __restrict__ dvf,
                                                       int n_dvf,
                                                       float* __restrict__ out) {
    extern __shared__ __align__(16) float dyn[];   // [2][RB][5][ROWF]
    __shared__ float red[8];
    __shared__ float red2[8];
    __shared__ bool is_last;

    const int t = threadIdx.x;
    const int blk = blockIdx.x;

    if (blk < NCC_BLOCKS) {
        // ───────────────────────── NCC block ─────────────────────────
        const int img = blk >> 5;       // 32 bands per image, 32 images
        const int band = blk & 31;
        const int r0 = band * BAND;
        const size_t base = (size_t)img * (WD * WD);
        const float* __restrict__ Ip = I + base;
        const float* __restrict__ Jp = J + base;

        // zero the horizontal padding (cols 0..3, 516..519) in BOTH buffers.
        // Disjoint from phaseA's writes (cols 4..515) -> published by the
        // pipeline's first barrier, no extra sync needed.
        if (t < 4) {
#pragma unroll
            for (int bu = 0; bu < 2; bu++)
#pragma unroll
                for (int rr = 0; rr < RB; rr++)
#pragma unroll
                    for (int q = 0; q < 5; q++) {
                        float* row = dyn + (size_t)(((bu * RB) + rr) * 5 + q) * ROWF;
                        row[t] = 0.0f;
                        row[516 + t] = 0.0f;
                    }
        }

        float acc;
        if (band >= 1 && band <= 30)
            acc = ncc_pipeline<false>(Ip, Jp, dyn, r0, t);   // guard-free fast path
        else
            acc = ncc_pipeline<true>(Ip, Jp, dyn, r0, t);    // bands 0 and 31

        // block reduction (8 warps)
#pragma unroll
        for (int d = 16; d > 0; d >>= 1) acc += __shfl_down_sync(0xffffffffu, acc, d);
        if ((t & 31) == 0) red[t >> 5] = acc;
        __syncthreads();
        if (t < 32) {
            float v = (t < 8) ? red[t] : 0.f;
#pragma unroll
            for (int d = 4; d > 0; d >>= 1) v += __shfl_down_sync(0xffffffffu, v, d);
            if (t == 0) atomicAdd(&g_acc[img & 1], (double)v);
        }
    } else {
        // ───────────────────────── grad block ─────────────────────────
        float adx = 0.f, ady = 0.f;
        const int gb = blk - NCC_BLOCKS;
        for (int idx = gb * 256 + t; idx < n_dvf; idx += GRAD_BLOCKS * 256) {
            const int hw = idx & 65535;           // position within one 256x256 map
            const float c = dvf[idx];
            if ((hw & 255) != 255) { float d = dvf[idx + 1] - c; adx += d * d; }
            if (hw < 65280)        { float d = dvf[idx + 256] - c; ady += d * d; }
        }
#pragma unroll
        for (int d = 16; d > 0; d >>= 1) {
            adx += __shfl_down_sync(0xffffffffu, adx, d);
            ady += __shfl_down_sync(0xffffffffu, ady, d);
        }
        if ((t & 31) == 0) { red[t >> 5] = adx; red2[t >> 5] = ady; }
        __syncthreads();
        if (t < 32) {
            float x = (t < 8) ? red[t] : 0.f;
            float y = (t < 8) ? red2[t] : 0.f;
#pragma unroll
            for (int d = 4; d > 0; d >>= 1) {
                x += __shfl_down_sync(0xffffffffu, x, d);
                y += __shfl_down_sync(0xffffffffu, y, d);
            }
            if (t == 0) {
                atomicAdd(&g_acc[2], (double)x);
                atomicAdd(&g_acc[3], (double)y);
            }
        }
    }

    // ───────────────── last-block finalize (graph-replay safe) ─────────────────
    __threadfence();
    if (t == 0) {
        unsigned int prev = atomicAdd(&g_count, 1u);
        is_last = (prev == (unsigned int)(TOTAL_BLOCKS - 1));
    }
    __syncthreads();
    if (is_last && t == 0) {
        // ncc = -(m0 + m1)/(C-1), C=2; m_c = sum_c / (B*H*W)
        double ncc = -(g_acc[0] + g_acc[1]) / (16.0 * 512.0 * 512.0);
        // grad = 0.01 * ((mean(dx^2)+mean(dy^2))/2 * 2.0)
        double Nd = 16.0 * 2.0 * 256.0 * 255.0;
        double grad = 0.01 * (g_acc[2] / Nd + g_acc[3] / Nd);
        out[0] = (float)(ncc + grad);
        out[1] = (float)ncc;
        out[2] = (float)grad;
        g_acc[0] = 0.0; g_acc[1] = 0.0; g_acc[2] = 0.0; g_acc[3] = 0.0;
        g_count = 0u;
    }
}

extern "C" void kernel_launch(void* const* d_in, const int* in_sizes, int n_in,
                              void* d_out, int out_size) {
    const float* y_true = (const float*)d_in[0];
    const float* y_pred = (const float*)d_in[1];
    const float* dvf    = (const float*)d_in[2];
    float* out = (float*)d_out;
    const int n_dvf = in_sizes[2];

    cudaFuncSetAttribute(fused_kernel, cudaFuncAttributeMaxDynamicSharedMemorySize,
                         SMEM_BYTES);
    fused_kernel<<<TOTAL_BLOCKS, 256, SMEM_BYTES>>>(y_true, y_pred, dvf, n_dvf, out);
}